// round 8
// baseline (speedup 1.0000x reference)
#include <cuda_runtime.h>
#include <cuda_fp16.h>
#include <cstdint>
#include <cstddef>

#define NDIM 1024
#define KDIM 256
#define BATCH 64   // B*R
#define RDIM 8

// Device-global scratch (no runtime allocation)
__device__ __half g_e[(size_t)BATCH * NDIM * KDIM];    // e = G@Bs, fp16
__device__ __half g_in[(size_t)BATCH * NDIM * KDIM];   // inputs, fp16
__device__ __half g_bsT[(size_t)RDIM * KDIM * KDIM];   // Bs transposed [r][g][f], fp16

__device__ __forceinline__ uint32_t smem_u32(const void* p) {
    uint32_t a;
    asm("{ .reg .u64 t; cvta.to.shared.u64 t, %1; cvt.u32.u64 %0, t; }" : "=r"(a) : "l"(p));
    return a;
}
__device__ __forceinline__ void cp16(uint32_t dst, const void* src) {
    asm volatile("cp.async.cg.shared.global [%0], [%1], 16;" :: "r"(dst), "l"(src));
}

#define LDMX4(r0, r1, r2, r3, addr)                                             \
    asm volatile("ldmatrix.sync.aligned.m8n8.x4.shared.b16 {%0,%1,%2,%3}, [%4];"\
        : "=r"(r0), "=r"(r1), "=r"(r2), "=r"(r3) : "r"(addr))

// m16n8k16 fp16 MMA, fp32 accum
#define MMA_F16(c, a, b)                                                        \
    asm volatile(                                                               \
        "mma.sync.aligned.m16n8k16.row.col.f32.f16.f16.f32 "                    \
        "{%0,%1,%2,%3}, {%4,%5,%6,%7}, {%8,%9}, {%0,%1,%2,%3};"                 \
        : "+f"((c)[0]), "+f"((c)[1]), "+f"((c)[2]), "+f"((c)[3])                \
        : "r"((a)[0]), "r"((a)[1]), "r"((a)[2]), "r"((a)[3]),                   \
          "r"((b)[0]), "r"((b)[1]))

// ---------------------------------------------------------------- pre-passes
__global__ void cvt_f2h(const float* __restrict__ in, __half* __restrict__ out, int n4) {
    int i = blockIdx.x * blockDim.x + threadIdx.x;
    if (i < n4) {
        float4 v = ((const float4*)in)[i];
        ((__half2*)out)[i * 2]     = __floats2half2_rn(v.x, v.y);
        ((__half2*)out)[i * 2 + 1] = __floats2half2_rn(v.z, v.w);
    }
}
__global__ void transpose_bs(const float* __restrict__ Bs, __half* __restrict__ BsT) {
    __shared__ float t[32][33];
    const int r = blockIdx.z;
    const int f0 = blockIdx.x * 32, g0 = blockIdx.y * 32;
    const int tx = threadIdx.x, ty = threadIdx.y;       // 32 x 8
    const float* src = Bs + (size_t)r * KDIM * KDIM;
    __half* dst = BsT + (size_t)r * KDIM * KDIM;
    for (int i = ty; i < 32; i += 8) t[i][tx] = src[(size_t)(f0 + i) * KDIM + g0 + tx];
    __syncthreads();
    for (int i = ty; i < 32; i += 8)
        dst[(size_t)(g0 + i) * KDIM + f0 + tx] = __float2half_rn(t[tx][i]);
}

// ---------------------------------------------------------------- fp16 mma GEMM
// C[128x128 tile] = A[128 x 256] (row-major fp16) @ B[128 x 256]^T (n-major fp16).
// 4 warps (2m x 2n), warp tile 64x64, m16n8k16, ldmatrix, 3-stage cp.async.
// Smem stage: 128 rows x 64 halves (128 B rows), XOR-16B swizzle; k-chunk = 64.
template<int EPI>   // 0: store fp16 (gemm1 -> g_e) ; 1: sigmoid fp32 (gemm2 -> out)
__global__ __launch_bounds__(128, 2)
void mma_gemm(const __half* __restrict__ Ab, const __half* __restrict__ Bb,
              void* __restrict__ Cb,
              int ldC, int bsel, size_t bStride, size_t cStride) {
    constexpr uint32_t STG = 128u * 128u;       // 16 KB per tile-stage
    constexpr uint32_t B_OFF = 3u * STG;
    constexpr int NCH = KDIM / 64;              // 4 k-chunks

    extern __shared__ char smem[];
    const uint32_t sb = smem_u32(smem);

    const int tid  = threadIdx.x;
    const int warp = tid >> 5, lane = tid & 31;
    const int wm = warp >> 1, wn = warp & 1;    // 2 x 2, warp tile 64x64
    const int tile_n = blockIdx.x, tile_m = blockIdx.y, br = blockIdx.z;

    const __half* A = Ab + (size_t)br * NDIM * KDIM + (size_t)tile_m * 128 * KDIM;
    const __half* B = Bb + (size_t)(bsel ? (br & 7) : br) * bStride + (size_t)tile_n * 128 * KDIM;

    float acc[4][8][4];
    #pragma unroll
    for (int i = 0; i < 4; i++)
        #pragma unroll
        for (int j = 0; j < 8; j++)
            #pragma unroll
            for (int q = 0; q < 4; q++) acc[i][j][q] = 0.f;

    // cp.async: 1024 16B-chunks per tile (128 rows x 8), 8 per thread
    auto load_chunk = [&](int c, int s) {
        const int k0 = c * 64;                  // halves
        const uint32_t ab = sb + (uint32_t)s * STG;
        const uint32_t bb = sb + B_OFF + (uint32_t)s * STG;
        #pragma unroll
        for (int j = 0; j < 8; j++) {
            const int idx = tid + j * 128;
            const int row = idx >> 3, cc = idx & 7;
            const uint32_t off = (uint32_t)(row * 128 + ((cc ^ (row & 7)) << 4));
            cp16(ab + off, A + (size_t)row * KDIM + k0 + cc * 8);
            cp16(bb + off, B + (size_t)row * KDIM + k0 + cc * 8);
        }
        asm volatile("cp.async.commit_group;" ::: "memory");
    };

    load_chunk(0, 0);
    load_chunk(1, 1);

    // ldmatrix lane decomposition (16B-chunk granular)
    const int l7 = lane & 7;
    const int arow_in16 = l7 + ((lane >> 3) & 1) * 8;
    const int pa = lane >> 4;                   // A: k-half of 16x16 fragment
    const int bnt_half = (lane >> 4) & 1;       // B: nt within x4
    const int pb = (lane >> 3) & 1;             // B: k-half

    #pragma unroll 1
    for (int c = 0; c < NCH; c++) {
        const int s = c - (c / 3) * 3;          // c % 3
        if (c + 2 < NCH) asm volatile("cp.async.wait_group 1;" ::: "memory");
        else             asm volatile("cp.async.wait_group 0;" ::: "memory");
        __syncthreads();

        const uint32_t Af = sb + (uint32_t)s * STG;
        const uint32_t Bf = sb + B_OFF + (uint32_t)s * STG;

        #pragma unroll
        for (int k16 = 0; k16 < 4; k16++) {     // 16 halves per step
            uint32_t a[4][4], b[8][2];
            #pragma unroll
            for (int mt = 0; mt < 4; mt++) {
                const int r = wm * 64 + mt * 16 + arow_in16;
                const uint32_t addr = Af + (uint32_t)(r * 128 + (((k16 * 2 + pa) ^ (r & 7)) << 4));
                LDMX4(a[mt][0], a[mt][1], a[mt][2], a[mt][3], addr);
            }
            #pragma unroll
            for (int q = 0; q < 4; q++) {       // each x4 covers 2 n8-tiles
                const int r = wn * 64 + (q * 2 + bnt_half) * 8 + l7;
                const uint32_t addr = Bf + (uint32_t)(r * 128 + (((k16 * 2 + pb) ^ (r & 7)) << 4));
                LDMX4(b[q * 2][0], b[q * 2][1], b[q * 2 + 1][0], b[q * 2 + 1][1], addr);
            }
            #pragma unroll
            for (int mt = 0; mt < 4; mt++)
                #pragma unroll
                for (int nt = 0; nt < 8; nt++)
                    MMA_F16(acc[mt][nt], a[mt], b[nt]);
        }

        if (c + 2 < NCH) load_chunk(c + 2, (c + 2) - ((c + 2) / 3) * 3);
    }

    // Epilogue: thread holds (r,c),(r,c+1),(r+8,c),(r+8,c+1) per (mt,nt)
    const int rbase = wm * 64 + (lane >> 2);
    const int cbase = wn * 64 + 2 * (lane & 3);
    if (EPI == 0) {
        __half* C = (__half*)Cb + (size_t)br * cStride +
                    (size_t)(tile_m * 128) * ldC + tile_n * 128;
        #pragma unroll
        for (int mt = 0; mt < 4; mt++) {
            const int r = rbase + mt * 16;
            #pragma unroll
            for (int nt = 0; nt < 8; nt++) {
                const int cc = cbase + nt * 8;
                *(__half2*)(C + (size_t)r * ldC + cc) =
                    __floats2half2_rn(acc[mt][nt][0], acc[mt][nt][1]);
                *(__half2*)(C + (size_t)(r + 8) * ldC + cc) =
                    __floats2half2_rn(acc[mt][nt][2], acc[mt][nt][3]);
            }
        }
    } else {
        float* C = (float*)Cb + (size_t)br * cStride +
                   (size_t)(tile_m * 128) * ldC + tile_n * 128;
        #pragma unroll
        for (int mt = 0; mt < 4; mt++) {
            const int r = rbase + mt * 16;
            #pragma unroll
            for (int nt = 0; nt < 8; nt++) {
                const int cc = cbase + nt * 8;
                float2 v0, v1;
                v0.x = 1.f / (1.f + __expf(-acc[mt][nt][0]));
                v0.y = 1.f / (1.f + __expf(-acc[mt][nt][1]));
                v1.x = 1.f / (1.f + __expf(-acc[mt][nt][2]));
                v1.y = 1.f / (1.f + __expf(-acc[mt][nt][3]));
                *(float2*)(C + (size_t)r * ldC + cc) = v0;
                *(float2*)(C + (size_t)(r + 8) * ldC + cc) = v1;
            }
        }
    }
}

// ---------------------------------------------------------------- launch
extern "C" void kernel_launch(void* const* d_in, const int* in_sizes, int n_in,
                              void* d_out, int out_size) {
    const float* inputs = (const float*)d_in[0];   // [8,8,1024,256]
    const float* Bw     = (const float*)d_in[1];   // [8,256,256]
    float* out          = (float*)d_out;           // [8,8,1024,1024]

    __half *pe, *pin, *pbsT;
    cudaGetSymbolAddress((void**)&pe,   g_e);
    cudaGetSymbolAddress((void**)&pin,  g_in);
    cudaGetSymbolAddress((void**)&pbsT, g_bsT);

    // fp16 pre-passes
    const int n4i = (BATCH * NDIM * KDIM) / 4;
    cvt_f2h<<<(n4i + 255) / 256, 256>>>(inputs, pin, n4i);
    transpose_bs<<<dim3(8, 8, 8), dim3(32, 8)>>>(Bw, pbsT);

    const size_t smemB = 6 * 128 * 128;   // 3 stages x (A 16K + B 16K) = 96 KB
    cudaFuncSetAttribute(mma_gemm<0>, cudaFuncAttributeMaxDynamicSharedMemorySize, (int)smemB);
    cudaFuncSetAttribute(mma_gemm<1>, cudaFuncAttributeMaxDynamicSharedMemorySize, (int)smemB);

    // GEMM1: e[1024,256] = in @ bsT^T  (fp16 out)
    mma_gemm<0><<<dim3(KDIM / 128, NDIM / 128, BATCH), 128, smemB>>>(
        pin, pbsT, pe,
        KDIM, /*bsel=*/1, (size_t)KDIM * KDIM, (size_t)NDIM * KDIM);

    // GEMM2: scores = e @ in^T ; sigmoid (fp32 out)
    mma_gemm<1><<<dim3(NDIM / 128, NDIM / 128, BATCH), 128, smemB>>>(
        pe, pin, out,
        NDIM, /*bsel=*/0, (size_t)NDIM * KDIM, (size_t)NDIM * NDIM);
}

// round 9
// speedup vs baseline: 1.2891x; 1.2891x over previous
#include <cuda_runtime.h>
#include <cuda_fp16.h>
#include <cstdint>
#include <cstddef>

#define NDIM 1024
#define KDIM 256
#define BATCH 64   // B*R
#define RDIM 8

// Device-global scratch (no runtime allocation)
__device__ __half g_e[(size_t)BATCH * NDIM * KDIM];    // e = G@Bs, fp16
__device__ __half g_in[(size_t)BATCH * NDIM * KDIM];   // inputs, fp16
__device__ __half g_bsT[(size_t)RDIM * KDIM * KDIM];   // Bs transposed [r][g][f], fp16

__device__ __forceinline__ uint32_t smem_u32(const void* p) {
    uint32_t a;
    asm("{ .reg .u64 t; cvta.to.shared.u64 t, %1; cvt.u32.u64 %0, t; }" : "=r"(a) : "l"(p));
    return a;
}
__device__ __forceinline__ void cp16(uint32_t dst, const void* src) {
    asm volatile("cp.async.cg.shared.global [%0], [%1], 16;" :: "r"(dst), "l"(src));
}

#define LDMX4(r0, r1, r2, r3, addr)                                             \
    asm volatile("ldmatrix.sync.aligned.m8n8.x4.shared.b16 {%0,%1,%2,%3}, [%4];"\
        : "=r"(r0), "=r"(r1), "=r"(r2), "=r"(r3) : "r"(addr))

// m16n8k16 fp16 MMA, fp32 accum
#define MMA_F16(c, a, b)                                                        \
    asm volatile(                                                               \
        "mma.sync.aligned.m16n8k16.row.col.f32.f16.f16.f32 "                    \
        "{%0,%1,%2,%3}, {%4,%5,%6,%7}, {%8,%9}, {%0,%1,%2,%3};"                 \
        : "+f"((c)[0]), "+f"((c)[1]), "+f"((c)[2]), "+f"((c)[3])                \
        : "r"((a)[0]), "r"((a)[1]), "r"((a)[2]), "r"((a)[3]),                   \
          "r"((b)[0]), "r"((b)[1]))

// ---------------------------------------------------------------- pre-passes
__global__ void cvt_f2h(const float* __restrict__ in, __half* __restrict__ out, int n4) {
    int i = blockIdx.x * blockDim.x + threadIdx.x;
    if (i < n4) {
        float4 v = ((const float4*)in)[i];
        ((__half2*)out)[i * 2]     = __floats2half2_rn(v.x, v.y);
        ((__half2*)out)[i * 2 + 1] = __floats2half2_rn(v.z, v.w);
    }
}
__global__ void transpose_bs(const float* __restrict__ Bs, __half* __restrict__ BsT) {
    __shared__ float t[32][33];
    const int r = blockIdx.z;
    const int f0 = blockIdx.x * 32, g0 = blockIdx.y * 32;
    const int tx = threadIdx.x, ty = threadIdx.y;       // 32 x 8
    const float* src = Bs + (size_t)r * KDIM * KDIM;
    __half* dst = BsT + (size_t)r * KDIM * KDIM;
    for (int i = ty; i < 32; i += 8) t[i][tx] = src[(size_t)(f0 + i) * KDIM + g0 + tx];
    __syncthreads();
    for (int i = ty; i < 32; i += 8)
        dst[(size_t)(g0 + i) * KDIM + f0 + tx] = __float2half_rn(t[tx][i]);
}

// ---------------------------------------------------------------- fp16 mma GEMM
// C[128x128 tile] = A[128 x 256] (row-major fp16) @ B[128 x 256]^T (n-major fp16).
// 8 warps (2m x 4n), warp tile 64x32, m16n8k16, ldmatrix, 3-stage cp.async.
// A-fragments double-buffered across k16 steps; next-chunk cp.async issued
// before the MMA block. Smem stage: 128 rows x 64 halves, XOR-16B swizzle.
template<int EPI>   // 0: store fp16 (gemm1 -> g_e) ; 1: sigmoid fp32 (gemm2 -> out)
__global__ __launch_bounds__(256, 2)
void mma_gemm(const __half* __restrict__ Ab, const __half* __restrict__ Bb,
              void* __restrict__ Cb,
              int ldC, int bsel, size_t bStride, size_t cStride) {
    constexpr uint32_t STG = 128u * 128u;       // 16 KB per tile-stage
    constexpr uint32_t B_OFF = 3u * STG;
    constexpr int NCH = KDIM / 64;              // 4 k-chunks

    extern __shared__ char smem[];
    const uint32_t sb = smem_u32(smem);

    const int tid  = threadIdx.x;
    const int warp = tid >> 5, lane = tid & 31;
    const int wm = warp >> 2, wn = warp & 3;    // 2 x 4, warp tile 64x32
    const int tile_n = blockIdx.x, tile_m = blockIdx.y, br = blockIdx.z;

    const __half* A = Ab + (size_t)br * NDIM * KDIM + (size_t)tile_m * 128 * KDIM;
    const __half* B = Bb + (size_t)(bsel ? (br & 7) : br) * bStride + (size_t)tile_n * 128 * KDIM;

    float acc[4][4][4];
    #pragma unroll
    for (int i = 0; i < 4; i++)
        #pragma unroll
        for (int j = 0; j < 4; j++)
            #pragma unroll
            for (int q = 0; q < 4; q++) acc[i][j][q] = 0.f;

    // cp.async: 1024 16B-chunks per tile (128 rows x 8), 4 per thread
    auto load_chunk = [&](int c, int s) {
        const int k0 = c * 64;                  // halves
        const uint32_t ab = sb + (uint32_t)s * STG;
        const uint32_t bb = sb + B_OFF + (uint32_t)s * STG;
        #pragma unroll
        for (int j = 0; j < 4; j++) {
            const int idx = tid + j * 256;
            const int row = idx >> 3, cc = idx & 7;
            const uint32_t off = (uint32_t)(row * 128 + ((cc ^ (row & 7)) << 4));
            cp16(ab + off, A + (size_t)row * KDIM + k0 + cc * 8);
            cp16(bb + off, B + (size_t)row * KDIM + k0 + cc * 8);
        }
        asm volatile("cp.async.commit_group;" ::: "memory");
    };

    load_chunk(0, 0);
    load_chunk(1, 1);

    // ldmatrix lane decomposition
    const int l7 = lane & 7;
    const int arow_in16 = l7 + ((lane >> 3) & 1) * 8;
    const int pa = lane >> 4;                   // A: k-half of 16x16 fragment
    const int bnt_half = (lane >> 4) & 1;       // B: nt within x4
    const int pb = (lane >> 3) & 1;             // B: k-half

    const int ar_row = wm * 64 + arow_in16;     // invariant A row base
    const int br_row = wn * 32 + bnt_half * 8 + l7;

    #pragma unroll 1
    for (int c = 0; c < NCH; c++) {
        const int s = c - (c / 3) * 3;          // c % 3
        if (c + 2 < NCH) asm volatile("cp.async.wait_group 1;" ::: "memory");
        else             asm volatile("cp.async.wait_group 0;" ::: "memory");
        __syncthreads();

        // issue next-next chunk's global loads before compute
        if (c + 2 < NCH) load_chunk(c + 2, (c + 2) - ((c + 2) / 3) * 3);

        const uint32_t Af = sb + (uint32_t)s * STG;
        const uint32_t Bf = sb + B_OFF + (uint32_t)s * STG;

        uint32_t a[2][4][4];                    // double-buffered A fragments

        // prefetch A for k16=0
        #pragma unroll
        for (int mt = 0; mt < 4; mt++) {
            const int r = ar_row + mt * 16;
            const uint32_t addr = Af + (uint32_t)(r * 128 + ((pa ^ (r & 7)) << 4));
            LDMX4(a[0][mt][0], a[0][mt][1], a[0][mt][2], a[0][mt][3], addr);
        }

        #pragma unroll
        for (int k16 = 0; k16 < 4; k16++) {
            const int cur = k16 & 1;
            uint32_t b[4][2];
            // B for this step
            #pragma unroll
            for (int q = 0; q < 2; q++) {
                const int r = br_row + q * 16;
                const uint32_t addr = Bf + (uint32_t)(r * 128 + (((k16 * 2 + pb) ^ (r & 7)) << 4));
                LDMX4(b[q * 2][0], b[q * 2][1], b[q * 2 + 1][0], b[q * 2 + 1][1], addr);
            }
            // A for next step
            if (k16 < 3) {
                #pragma unroll
                for (int mt = 0; mt < 4; mt++) {
                    const int r = ar_row + mt * 16;
                    const uint32_t addr = Af +
                        (uint32_t)(r * 128 + ((((k16 + 1) * 2 + pa) ^ (r & 7)) << 4));
                    LDMX4(a[cur ^ 1][mt][0], a[cur ^ 1][mt][1],
                          a[cur ^ 1][mt][2], a[cur ^ 1][mt][3], addr);
                }
            }
            #pragma unroll
            for (int mt = 0; mt < 4; mt++)
                #pragma unroll
                for (int nt = 0; nt < 4; nt++)
                    MMA_F16(acc[mt][nt], a[cur][mt], b[nt]);
        }
    }

    // Epilogue: thread holds (r,c),(r,c+1),(r+8,c),(r+8,c+1) per (mt,nt)
    const int rbase = wm * 64 + (lane >> 2);
    const int cbase = wn * 32 + 2 * (lane & 3);
    if (EPI == 0) {
        __half* C = (__half*)Cb + (size_t)br * cStride +
                    (size_t)(tile_m * 128) * ldC + tile_n * 128;
        #pragma unroll
        for (int mt = 0; mt < 4; mt++) {
            const int r = rbase + mt * 16;
            #pragma unroll
            for (int nt = 0; nt < 4; nt++) {
                const int cc = cbase + nt * 8;
                *(__half2*)(C + (size_t)r * ldC + cc) =
                    __floats2half2_rn(acc[mt][nt][0], acc[mt][nt][1]);
                *(__half2*)(C + (size_t)(r + 8) * ldC + cc) =
                    __floats2half2_rn(acc[mt][nt][2], acc[mt][nt][3]);
            }
        }
    } else {
        float* C = (float*)Cb + (size_t)br * cStride +
                   (size_t)(tile_m * 128) * ldC + tile_n * 128;
        #pragma unroll
        for (int mt = 0; mt < 4; mt++) {
            const int r = rbase + mt * 16;
            #pragma unroll
            for (int nt = 0; nt < 4; nt++) {
                const int cc = cbase + nt * 8;
                float2 v0, v1;
                v0.x = 1.f / (1.f + __expf(-acc[mt][nt][0]));
                v0.y = 1.f / (1.f + __expf(-acc[mt][nt][1]));
                v1.x = 1.f / (1.f + __expf(-acc[mt][nt][2]));
                v1.y = 1.f / (1.f + __expf(-acc[mt][nt][3]));
                *(float2*)(C + (size_t)r * ldC + cc) = v0;
                *(float2*)(C + (size_t)(r + 8) * ldC + cc) = v1;
            }
        }
    }
}

// ---------------------------------------------------------------- launch
extern "C" void kernel_launch(void* const* d_in, const int* in_sizes, int n_in,
                              void* d_out, int out_size) {
    const float* inputs = (const float*)d_in[0];   // [8,8,1024,256]
    const float* Bw     = (const float*)d_in[1];   // [8,256,256]
    float* out          = (float*)d_out;           // [8,8,1024,1024]

    __half *pe, *pin, *pbsT;
    cudaGetSymbolAddress((void**)&pe,   g_e);
    cudaGetSymbolAddress((void**)&pin,  g_in);
    cudaGetSymbolAddress((void**)&pbsT, g_bsT);

    // fp16 pre-passes
    const int n4i = (BATCH * NDIM * KDIM) / 4;
    cvt_f2h<<<(n4i + 255) / 256, 256>>>(inputs, pin, n4i);
    transpose_bs<<<dim3(8, 8, 8), dim3(32, 8)>>>(Bw, pbsT);

    const size_t smemB = 6 * 128 * 128;   // 3 stages x (A 16K + B 16K) = 96 KB
    cudaFuncSetAttribute(mma_gemm<0>, cudaFuncAttributeMaxDynamicSharedMemorySize, (int)smemB);
    cudaFuncSetAttribute(mma_gemm<1>, cudaFuncAttributeMaxDynamicSharedMemorySize, (int)smemB);

    // GEMM1: e[1024,256] = in @ bsT^T  (fp16 out)
    mma_gemm<0><<<dim3(KDIM / 128, NDIM / 128, BATCH), 256, smemB>>>(
        pin, pbsT, pe,
        KDIM, /*bsel=*/1, (size_t)KDIM * KDIM, (size_t)NDIM * KDIM);

    // GEMM2: scores = e @ in^T ; sigmoid (fp32 out)
    mma_gemm<1><<<dim3(NDIM / 128, NDIM / 128, BATCH), 256, smemB>>>(
        pe, pin, out,
        NDIM, /*bsel=*/0, (size_t)NDIM * KDIM, (size_t)NDIM * NDIM);
}